// round 10
// baseline (speedup 1.0000x reference)
#include <cuda_runtime.h>

// topk_mean (k=2) segment pooling.
// h: [BS, SEQ, EMB] fp32, patch_ids: [BS, SEQ] int32 sorted ascending per batch.
// out: [BS, PNUM, EMB] fp32.
// Semantics (faithful to reference tie-masking loop):
//   max1 = segment max; max2 = max over values strictly != max1 (or -1e9 if none)
//   count==0 -> 0 ; count==1 -> max1 ; count>=2 -> (max1 + max2)/2

#define BS   8
#define SEQ  4096
#define EMB  512
#define PNUM 1024
#define EV4  (EMB / 4)          /* 128 float4 per row */
#define WPP  4                  /* warps per CTA = patches per CTA */
#define NEG_INF_V (-1.0e9f)

// starts[b][p] = first token index t with patch_ids[b][t] >= p; starts[b][PNUM]=SEQ.
__device__ int g_starts[BS * (PNUM + 1)];

__global__ void starts_kernel(const int* __restrict__ pid) {
    const int b = blockIdx.y;
    const int t = blockIdx.x * blockDim.x + threadIdx.x;
    if (t >= SEQ) return;
    const int* __restrict__ p = pid + b * SEQ;
    int* __restrict__ st = g_starts + b * (PNUM + 1);

    const int cur  = p[t];
    const int prev = (t == 0) ? -1 : p[t - 1];
    for (int q = prev + 1; q <= cur; ++q) st[q] = t;
    if (t == SEQ - 1) {
        for (int q = cur + 1; q <= PNUM; ++q) st[q] = SEQ;
    }
}

// Running top-2 with tie-skip: v == m1 leaves m2 unchanged.
__device__ __forceinline__ void upd1(float v, float& m1, float& m2) {
    const float nm2 = (v > m1) ? m1 : ((v < m1) ? fmaxf(m2, v) : m2);
    m1 = fmaxf(m1, v);
    m2 = nm2;
}
__device__ __forceinline__ void upd4(const float4 v, float4& m1, float4& m2) {
    upd1(v.x, m1.x, m2.x);
    upd1(v.y, m1.y, m2.y);
    upd1(v.z, m1.z, m2.z);
    upd1(v.w, m1.w, m2.w);
}

__device__ __forceinline__ float4 fin4(const float4 m1, const float4 m2) {
    float4 r;
    r.x = 0.5f * (m1.x + ((m2.x == -INFINITY) ? NEG_INF_V : m2.x));
    r.y = 0.5f * (m1.y + ((m2.y == -INFINITY) ? NEG_INF_V : m2.y));
    r.z = 0.5f * (m1.z + ((m2.z == -INFINITY) ? NEG_INF_V : m2.z));
    r.w = 0.5f * (m1.w + ((m2.w == -INFINITY) ? NEG_INF_V : m2.w));
    return r;
}

// One warp per (b, p). Each lane owns float4 slots {lane, lane+32, lane+64,
// lane+96}: every LDG.128 is warp-coalesced (512B), and each token step
// issues 4 independent loads (MLP=4 by layout, no prefetch code).
__global__ __launch_bounds__(128, 8)
void pool_kernel(const float4* __restrict__ h4, float4* __restrict__ out4) {
    const int lane = threadIdx.x & 31;
    const int wid  = threadIdx.x >> 5;
    const int p = blockIdx.x * WPP + wid;
    const int b = blockIdx.y;

    const int* __restrict__ st = g_starts + b * (PNUM + 1);
    const int start = st[p];
    const int cnt   = st[p + 1] - start;

    float4* __restrict__ o =
        out4 + ((size_t)(b * PNUM + p)) * EV4 + lane;

    if (cnt == 0) {
        const float4 z = make_float4(0.f, 0.f, 0.f, 0.f);
        o[0] = z; o[32] = z; o[64] = z; o[96] = z;
        return;
    }

    const float4* __restrict__ hb =
        h4 + ((size_t)b * SEQ + start) * EV4 + lane;

    // Row 0 initializes m1 directly (cnt==1 exits with no extra work).
    float4 m1a = hb[0], m1b = hb[32], m1c = hb[64], m1d = hb[96];
    if (cnt == 1) {
        o[0] = m1a; o[32] = m1b; o[64] = m1c; o[96] = m1d;
        return;
    }

    const float4 ninf = make_float4(-INFINITY, -INFINITY, -INFINITY, -INFINITY);
    float4 m2a = ninf, m2b = ninf, m2c = ninf, m2d = ninf;

    for (int t = 1; t < cnt; ++t) {
        const size_t base = (size_t)t * EV4;
        const float4 va = hb[base];
        const float4 vb = hb[base + 32];
        const float4 vc = hb[base + 64];
        const float4 vd = hb[base + 96];
        upd4(va, m1a, m2a);
        upd4(vb, m1b, m2b);
        upd4(vc, m1c, m2c);
        upd4(vd, m1d, m2d);
    }

    o[0]  = fin4(m1a, m2a);
    o[32] = fin4(m1b, m2b);
    o[64] = fin4(m1c, m2c);
    o[96] = fin4(m1d, m2d);
}

extern "C" void kernel_launch(void* const* d_in, const int* in_sizes, int n_in,
                              void* d_out, int out_size) {
    const float* h   = (const float*)d_in[0];
    const int*   pid = (const int*)d_in[1];
    float*       out = (float*)d_out;

    (void)in_sizes; (void)n_in; (void)out_size;

    dim3 g1((SEQ + 255) / 256, BS);
    starts_kernel<<<g1, 256>>>(pid);

    dim3 g2(PNUM / WPP, BS);
    pool_kernel<<<g2, 128>>>((const float4*)h, (float4*)out);
}

// round 15
// speedup vs baseline: 1.1199x; 1.1199x over previous
#include <cuda_runtime.h>

// topk_mean (k=2) segment pooling.
// h: [BS, SEQ, EMB] fp32, patch_ids: [BS, SEQ] int32 sorted ascending per batch.
// out: [BS, PNUM, EMB] fp32.
// Semantics (faithful to reference tie-masking loop):
//   max1 = segment max; max2 = max over values strictly != max1 (or -1e9 if none)
//   count==0 -> 0 ; count==1 -> max1 ; count>=2 -> (max1 + max2)/2

#define BS   8
#define SEQ  4096
#define EMB  512
#define PNUM 1024
#define EV4  (EMB / 4)          /* 128 float4 per row */
#define NEG_INF_V (-1.0e9f)

// starts[b][p] = first token index t with patch_ids[b][t] >= p; starts[b][PNUM]=SEQ.
__device__ int g_starts[BS * (PNUM + 1)];

__global__ void starts_kernel(const int* __restrict__ pid) {
    const int b = blockIdx.y;
    const int t = blockIdx.x * blockDim.x + threadIdx.x;
    if (t >= SEQ) return;
    const int* __restrict__ p = pid + b * SEQ;
    int* __restrict__ st = g_starts + b * (PNUM + 1);

    const int cur  = p[t];
    const int prev = (t == 0) ? -1 : p[t - 1];
    for (int q = prev + 1; q <= cur; ++q) st[q] = t;
    if (t == SEQ - 1) {
        for (int q = cur + 1; q <= PNUM; ++q) st[q] = SEQ;
    }
}

// Running top-2 with tie-skip: v == m1 leaves m2 unchanged.
__device__ __forceinline__ void upd1(float v, float& m1, float& m2) {
    const float nm2 = (v > m1) ? m1 : ((v < m1) ? fmaxf(m2, v) : m2);
    m1 = fmaxf(m1, v);
    m2 = nm2;
}
__device__ __forceinline__ void upd4(const float4 v, float4& m1, float4& m2) {
    upd1(v.x, m1.x, m2.x);
    upd1(v.y, m1.y, m2.y);
    upd1(v.z, m1.z, m2.z);
    upd1(v.w, m1.w, m2.w);
}

__device__ __forceinline__ float4 fin4(const float4 m1, const float4 m2) {
    float4 r;
    r.x = 0.5f * (m1.x + ((m2.x == -INFINITY) ? NEG_INF_V : m2.x));
    r.y = 0.5f * (m1.y + ((m2.y == -INFINITY) ? NEG_INF_V : m2.y));
    r.z = 0.5f * (m1.z + ((m2.z == -INFINITY) ? NEG_INF_V : m2.z));
    r.w = 0.5f * (m1.w + ((m2.w == -INFINITY) ? NEG_INF_V : m2.w));
    return r;
}

// One 64-thread CTA per (b, p). Each thread owns float4 slots {tid, tid+64}:
// both LDG.128 per token step are warp-coalesced and mutually independent
// (MLP=2 by layout, no prefetch code, no remainder paths).
__global__ __launch_bounds__(64)
void pool_kernel(const float4* __restrict__ h4, float4* __restrict__ out4) {
    const int p   = blockIdx.x;
    const int b   = blockIdx.y;
    const int tid = threadIdx.x;

    const int* __restrict__ st = g_starts + b * (PNUM + 1);
    const int start = st[p];
    const int cnt   = st[p + 1] - start;

    float4* __restrict__ o =
        out4 + ((size_t)(b * PNUM + p)) * EV4 + tid;

    if (cnt == 0) {
        const float4 z = make_float4(0.f, 0.f, 0.f, 0.f);
        o[0] = z; o[64] = z;
        return;
    }

    const float4* __restrict__ hb =
        h4 + ((size_t)b * SEQ + start) * EV4 + tid;

    // Row 0 initializes m1 directly (cnt==1 exits with no extra work).
    float4 m1a = hb[0];
    float4 m1b = hb[64];
    if (cnt == 1) {
        o[0] = m1a; o[64] = m1b;
        return;
    }

    const float4 ninf = make_float4(-INFINITY, -INFINITY, -INFINITY, -INFINITY);
    float4 m2a = ninf, m2b = ninf;

    for (int t = 1; t < cnt; ++t) {
        const size_t base = (size_t)t * EV4;
        const float4 va = hb[base];
        const float4 vb = hb[base + 64];
        upd4(va, m1a, m2a);
        upd4(vb, m1b, m2b);
    }

    o[0]  = fin4(m1a, m2a);
    o[64] = fin4(m1b, m2b);
}

extern "C" void kernel_launch(void* const* d_in, const int* in_sizes, int n_in,
                              void* d_out, int out_size) {
    const float* h   = (const float*)d_in[0];
    const int*   pid = (const int*)d_in[1];
    float*       out = (float*)d_out;

    (void)in_sizes; (void)n_in; (void)out_size;

    dim3 g1((SEQ + 255) / 256, BS);
    starts_kernel<<<g1, 256>>>(pid);

    dim3 g2(PNUM, BS);
    pool_kernel<<<g2, 64>>>((const float4*)h, (float4*)out);
}

// round 16
// speedup vs baseline: 1.2581x; 1.1233x over previous
#include <cuda_runtime.h>

// topk_mean (k=2) segment pooling.
// h: [BS, SEQ, EMB] fp32, patch_ids: [BS, SEQ] int32 sorted ascending per batch.
// out: [BS, PNUM, EMB] fp32.
// Semantics (faithful to reference tie-masking loop):
//   max1 = segment max; max2 = max over values strictly != max1 (or -1e9 if none)
//   count==0 -> 0 ; count==1 -> max1 ; count>=2 -> (max1 + max2)/2

#define BS    8
#define SEQ   4096
#define EMB   512
#define PNUM  1024
#define EV4   (EMB / 4)         /* 128 float4 per row */
#define BATCH 8                 /* rows staged in flight per CTA batch */
#define NEG_INF_V (-1.0e9f)

// bounds[b][p] = {start, end}: token range of patch p (patch_ids sorted).
__device__ int2 g_bounds[BS * PNUM];

__global__ void starts_kernel(const int* __restrict__ pid) {
    const int b = blockIdx.y;
    const int t = blockIdx.x * blockDim.x + threadIdx.x;
    if (t >= SEQ) return;
    const int* __restrict__ p = pid + b * SEQ;
    int2* __restrict__ bd = g_bounds + b * PNUM;

    const int cur  = p[t];
    const int prev = (t == 0) ? -1 : p[t - 1];
    // virtual starts s[q]: s[q]=t for q in (prev, cur]; bounds[q] = (s[q], s[q+1])
    for (int q = prev + 1; q <= cur; ++q) {
        bd[q].x = t;                    // q <= cur < PNUM
        if (q >= 1) bd[q - 1].y = t;
    }
    if (t == SEQ - 1) {
        for (int q = cur + 1; q <= PNUM; ++q) {
            if (q < PNUM) bd[q].x = SEQ;
            bd[q - 1].y = SEQ;
        }
    }
}

// Running top-2 with tie-skip: v == m1 leaves m2 unchanged (reference masks
// ALL positions equal to max1 before the second max).
__device__ __forceinline__ void upd1(float v, float& m1, float& m2) {
    if (v > m1)                { m2 = m1; m1 = v; }
    else if (v < m1 && v > m2) { m2 = v; }
}
__device__ __forceinline__ void upd4(const float4 v, float4& m1, float4& m2) {
    upd1(v.x, m1.x, m2.x);
    upd1(v.y, m1.y, m2.y);
    upd1(v.z, m1.z, m2.z);
    upd1(v.w, m1.w, m2.w);
}

__device__ __forceinline__ void cp_async16(unsigned smem_addr, const void* gmem) {
    asm volatile("cp.async.cg.shared.global [%0], [%1], 16;\n"
                 :: "r"(smem_addr), "l"(gmem));
}

// One 128-thread CTA per (b, p); thread owns one float4 lane. Token rows are
// staged through smem with cp.async so up to BATCH rows (16 KB) are in flight
// per CTA without holding load-destination registers.
__global__ __launch_bounds__(128)
void pool_kernel(const float4* __restrict__ h4, float4* __restrict__ out4) {
    __shared__ float4 buf[BATCH][128];

    const int p   = blockIdx.x;
    const int b   = blockIdx.y;
    const int tid = threadIdx.x;

    const int2 be  = g_bounds[b * PNUM + p];
    const int  cnt = be.y - be.x;

    float4* __restrict__ o =
        out4 + ((size_t)(b * PNUM + p)) * EV4 + tid;

    if (cnt == 0) {
        *o = make_float4(0.f, 0.f, 0.f, 0.f);
        return;
    }

    const float4* __restrict__ hb =
        h4 + ((size_t)b * SEQ + be.x) * EV4 + tid;

    const unsigned sbase =
        (unsigned)__cvta_generic_to_shared(&buf[0][tid]);

    const float4 ninf = make_float4(-INFINITY, -INFINITY, -INFINITY, -INFINITY);
    float4 m1 = ninf, m2 = ninf;

    int t = 0;
    for (;;) {
        int batch = cnt - t;
        if (batch > BATCH) batch = BATCH;

        // Stage up to BATCH rows: independent 16B cp.asyncs, one wait.
        #pragma unroll
        for (int i = 0; i < BATCH; ++i) {
            if (i < batch)
                cp_async16(sbase + i * (128 * 16),
                           hb + (size_t)(t + i) * EV4);
        }
        asm volatile("cp.async.commit_group;\n" ::: "memory");
        asm volatile("cp.async.wait_group 0;\n"  ::: "memory");

        // Each thread consumes only its own staged 16B -> no __syncthreads.
        #pragma unroll
        for (int i = 0; i < BATCH; ++i) {
            if (i < batch) {
                const float4 v = buf[i][tid];
                upd4(v, m1, m2);
            }
        }

        t += batch;
        if (t >= cnt) break;
    }

    float4 r;
    if (cnt == 1) {
        r = m1;
    } else {
        r.x = 0.5f * (m1.x + ((m2.x == -INFINITY) ? NEG_INF_V : m2.x));
        r.y = 0.5f * (m1.y + ((m2.y == -INFINITY) ? NEG_INF_V : m2.y));
        r.z = 0.5f * (m1.z + ((m2.z == -INFINITY) ? NEG_INF_V : m2.z));
        r.w = 0.5f * (m1.w + ((m2.w == -INFINITY) ? NEG_INF_V : m2.w));
    }
    *o = r;
}

extern "C" void kernel_launch(void* const* d_in, const int* in_sizes, int n_in,
                              void* d_out, int out_size) {
    const float* h   = (const float*)d_in[0];
    const int*   pid = (const int*)d_in[1];
    float*       out = (float*)d_out;

    (void)in_sizes; (void)n_in; (void)out_size;

    dim3 g1((SEQ + 255) / 256, BS);
    starts_kernel<<<g1, 256>>>(pid);

    dim3 g2(PNUM, BS);
    pool_kernel<<<g2, 128>>>((const float4*)h, (float4*)out);
}